// round 9
// baseline (speedup 1.0000x reference)
#include <cuda_runtime.h>
#include <math.h>

#define TT 128
#define BSZ 128
#define NV 32
#define SD 64

typedef unsigned long long ull;

// Gain matrices K_t (only t <= g_tc valid), layout K[t][(s)*32 + v]
__device__ float g_K[(TT - 1) * SD * NV];
// Combined step operators G_t = [[A,B],[HA,HB]], float4-chunk-major:
// element (row r, col c) of G_t at g_G[t*9216 + (c>>2)*384 + r*4 + (c&3)]
__device__ float g_G[(TT - 1) * 96 * 96];
// Convergence step (last distinct t)
__device__ int g_tc;

__device__ __forceinline__ ull pack2(float x, float y) {
    ull r; asm("mov.b64 %0, {%1, %2};" : "=l"(r) : "f"(x), "f"(y)); return r;
}
__device__ __forceinline__ ull ffma2(ull a, ull b, ull c) {
    ull d; asm("fma.rn.f32x2 %0, %1, %2, %3;" : "=l"(d) : "l"(a), "l"(b), "l"(c));
    return d;
}
__device__ __forceinline__ void unpack2(ull a, float& x, float& y) {
    asm("mov.b64 {%0, %1}, %2;" : "=f"(x), "=f"(y) : "l"(a));
}

// General 4x4 inverse via 2x2 block Schur complement (SPD-safe, no pivoting).
__device__ __forceinline__ void inv4(const float M[4][4], float O[4][4])
{
    float a = M[0][0], b = M[0][1], c = M[1][0], d = M[1][1];
    float idet = 1.0f / (a * d - b * c);
    float Ai00 =  d * idet, Ai01 = -b * idet;
    float Ai10 = -c * idet, Ai11 =  a * idet;
    float B00 = M[0][2], B01 = M[0][3], B10 = M[1][2], B11 = M[1][3];
    float C00 = M[2][0], C01 = M[2][1], C10 = M[3][0], C11 = M[3][1];
    float D00 = M[2][2], D01 = M[2][3], D10 = M[3][2], D11 = M[3][3];
    float AB00 = Ai00 * B00 + Ai01 * B10, AB01 = Ai00 * B01 + Ai01 * B11;
    float AB10 = Ai10 * B00 + Ai11 * B10, AB11 = Ai10 * B01 + Ai11 * B11;
    float CA00 = C00 * Ai00 + C01 * Ai10, CA01 = C00 * Ai01 + C01 * Ai11;
    float CA10 = C10 * Ai00 + C11 * Ai10, CA11 = C10 * Ai01 + C11 * Ai11;
    float S00 = D00 - (C00 * AB00 + C01 * AB10);
    float S01 = D01 - (C00 * AB01 + C01 * AB11);
    float S10 = D10 - (C10 * AB00 + C11 * AB10);
    float S11 = D11 - (C10 * AB01 + C11 * AB11);
    float sdet = 1.0f / (S00 * S11 - S01 * S10);
    float Si00 =  S11 * sdet, Si01 = -S01 * sdet;
    float Si10 = -S10 * sdet, Si11 =  S00 * sdet;
    float SC00 = Si00 * CA00 + Si01 * CA10, SC01 = Si00 * CA01 + Si01 * CA11;
    float SC10 = Si10 * CA00 + Si11 * CA10, SC11 = Si10 * CA01 + Si11 * CA11;
    float AS00 = AB00 * Si00 + AB01 * Si10, AS01 = AB00 * Si01 + AB01 * Si11;
    float AS10 = AB10 * Si00 + AB11 * Si10, AS11 = AB10 * Si01 + AB11 * Si11;
    O[0][0] = Ai00 + AS00 * CA00 + AS01 * CA10;
    O[0][1] = Ai01 + AS00 * CA01 + AS01 * CA11;
    O[1][0] = Ai10 + AS10 * CA00 + AS11 * CA10;
    O[1][1] = Ai11 + AS10 * CA01 + AS11 * CA11;
    O[0][2] = -AS00; O[0][3] = -AS01;
    O[1][2] = -AS10; O[1][3] = -AS11;
    O[2][0] = -SC00; O[2][1] = -SC01;
    O[3][0] = -SC10; O[3][1] = -SC11;
    O[2][2] = Si00; O[2][3] = Si01;
    O[3][2] = Si10; O[3][3] = Si11;
}

// ---------------------------------------------------------------------------
// Phase 1: single CTA, 256 threads. Riccati via the refactored identity
//   P' = (F P F^T + Q) - M Z,  M = F*PHt,  Z = S^-1 M^T,
// so all big matmuls (FP, FPFt, M) run BEFORE / beside the S-solve and the
// post-solve serial tail is one small symmetric product. 12 barriers/step.
// ---------------------------------------------------------------------------
__global__ __launch_bounds__(256, 1) void kf_phase1(
    const float* __restrict__ Fm, const float* __restrict__ Hm,
    const float* __restrict__ Rm, const float* __restrict__ Qm)
{
    extern __shared__ float sm[];
    float* F2f  = sm;                   // [64][66] dup (ull view)
    float* Ft   = F2f + 64 * 66 * 2;    // [64][66]  Ft[k][j] = F[j][k]
    float* sH   = Ft  + 64 * 66;        // [32][66]
    float* P    = sH  + 32 * 66;        // [64][66]  (also holds FPFt mid-step)
    float* FPdf = P   + 64 * 66;        // [64][66] dup (ull view)
    float* FPp  = FPdf + 64 * 66 * 2;   // [64][66] plain
    float* PHt  = FPp + 64 * 66;        // [64][33]
    float* Mdf  = PHt + 64 * 33;        // [64][33] dup of -M (ull view)
    float* aug  = Mdf + 64 * 33 * 2;    // [32][162]  (S | PHt^T | M^T)
    float* Zbuf = aug + 32 * 162;       // [32][66]
    float* Kb   = Zbuf + 32 * 66;       // [64*32]
    int*   red  = (int*)(Kb + 64 * 32); // [1]
    ull* F2  = (ull*)F2f;
    ull* FPd = (ull*)FPdf;
    ull* Md  = (ull*)Mdf;

    const int tid = threadIdx.x;
    if (tid == 0) g_tc = TT - 2;

    // Lower-triangle 4x4-tile mapping for tid < 136
    int tri_i = 0, tri_j = 0;
    {
        int q = (tid < 136) ? tid : 0;
        tri_i = (int)((sqrtf(8.0f * (float)q + 1.0f) - 1.0f) * 0.5f);
        while ((tri_i + 1) * (tri_i + 2) / 2 <= q) ++tri_i;
        while (tri_i * (tri_i + 1) / 2 > q) --tri_i;
        tri_j = q - tri_i * (tri_i + 1) / 2;
    }

    for (int idx = tid; idx < 64 * 64; idx += 256) {
        int i = idx >> 6, j = idx & 63;
        float f = Fm[idx];
        F2[i * 66 + j] = pack2(f, f);
        Ft[j * 66 + i] = f;
        P [i * 66 + j] = (i == j) ? 1.0f : 0.0f;
    }
    for (int idx = tid; idx < 32 * 64; idx += 256) {
        int i = idx >> 6, j = idx & 63;
        sH[i * 66 + j] = Hm[idx];
    }
    for (int idx = tid; idx < 64 * 32; idx += 256) Kb[idx] = 1e30f;
    __syncthreads();

    for (int t = 0; t < TT - 1; ++t) {
        // ======== Phase 1: PHt = P H^T (k-packed)  and  FP = F P ========
        {   // A: PHt 4x2 tiles, k-contraction f32x2
            int i0 = (tid >> 4) * 4, v0 = (tid & 15) * 2;
            ull acc[4][2];
            #pragma unroll
            for (int r = 0; r < 4; ++r) { acc[r][0] = 0ull; acc[r][1] = 0ull; }
            #pragma unroll 4
            for (int k2 = 0; k2 < 32; ++k2) {
                ull h0 = *(const ull*)&sH[v0 * 66 + 2 * k2];
                ull h1 = *(const ull*)&sH[(v0 + 1) * 66 + 2 * k2];
                #pragma unroll
                for (int r = 0; r < 4; ++r) {
                    ull p = *(const ull*)&P[(i0 + r) * 66 + 2 * k2];
                    acc[r][0] = ffma2(p, h0, acc[r][0]);
                    acc[r][1] = ffma2(p, h1, acc[r][1]);
                }
            }
            #pragma unroll
            for (int r = 0; r < 4; ++r) {
                float x0, y0, x1, y1;
                unpack2(acc[r][0], x0, y0); unpack2(acc[r][1], x1, y1);
                float pv0 = x0 + y0, pv1 = x1 + y1;
                PHt[(i0 + r) * 33 + v0    ] = pv0;
                PHt[(i0 + r) * 33 + v0 + 1] = pv1;
                aug[v0 * 162 + 32 + i0 + r] = pv0;
                aug[(v0 + 1) * 162 + 32 + i0 + r] = pv1;
            }
        }
        {   // B: FP = F @ P (f32x2, F duplicated, P j-paired); dup+plain out
            int i0 = (tid >> 4) * 4, j0 = (tid & 15) * 4;
            ull acc[4][2];
            #pragma unroll
            for (int r = 0; r < 4; ++r) { acc[r][0] = 0ull; acc[r][1] = 0ull; }
            #pragma unroll 4
            for (int k = 0; k < 64; ++k) {
                ull b0 = *(const ull*)&P[k * 66 + j0];
                ull b1 = *(const ull*)&P[k * 66 + j0 + 2];
                #pragma unroll
                for (int r = 0; r < 4; ++r) {
                    ull a = F2[(i0 + r) * 66 + k];
                    acc[r][0] = ffma2(a, b0, acc[r][0]);
                    acc[r][1] = ffma2(a, b1, acc[r][1]);
                }
            }
            #pragma unroll
            for (int r = 0; r < 4; ++r) {
                float v0, v1, v2, v3;
                unpack2(acc[r][0], v0, v1); unpack2(acc[r][1], v2, v3);
                FPd[(i0 + r) * 66 + j0    ] = pack2(v0, v0);
                FPd[(i0 + r) * 66 + j0 + 1] = pack2(v1, v1);
                FPd[(i0 + r) * 66 + j0 + 2] = pack2(v2, v2);
                FPd[(i0 + r) * 66 + j0 + 3] = pack2(v3, v3);
                FPp[(i0 + r) * 66 + j0    ] = v0;
                FPp[(i0 + r) * 66 + j0 + 1] = v1;
                FPp[(i0 + r) * 66 + j0 + 2] = v2;
                FPp[(i0 + r) * 66 + j0 + 3] = v3;
            }
        }
        __syncthreads();

        // ======== Phase 2: S = H PHt + R ; M = FP H^T ; FPFt = FP F^T + Q ==
        {   // S (scalar)
            int i  = tid >> 3;
            int j0 = (tid & 7) * 4;
            float c0 = 0, c1 = 0, c2 = 0, c3 = 0;
            #pragma unroll 8
            for (int k = 0; k < 64; ++k) {
                float a = sH[i * 66 + k];
                const float* bp = &PHt[k * 33 + j0];
                c0 += a * bp[0]; c1 += a * bp[1];
                c2 += a * bp[2]; c3 += a * bp[3];
            }
            aug[i * 162 + j0    ] = c0 + Rm[i * 32 + j0    ];
            aug[i * 162 + j0 + 1] = c1 + Rm[i * 32 + j0 + 1];
            aug[i * 162 + j0 + 2] = c2 + Rm[i * 32 + j0 + 2];
            aug[i * 162 + j0 + 3] = c3 + Rm[i * 32 + j0 + 3];
        }
        {   // M = FP @ H^T (k-packed); M^T into aug, -M dup into Md
            int i0 = (tid >> 4) * 4, v0 = (tid & 15) * 2;
            ull acc[4][2];
            #pragma unroll
            for (int r = 0; r < 4; ++r) { acc[r][0] = 0ull; acc[r][1] = 0ull; }
            #pragma unroll 4
            for (int k2 = 0; k2 < 32; ++k2) {
                ull h0 = *(const ull*)&sH[v0 * 66 + 2 * k2];
                ull h1 = *(const ull*)&sH[(v0 + 1) * 66 + 2 * k2];
                #pragma unroll
                for (int r = 0; r < 4; ++r) {
                    ull p = *(const ull*)&FPp[(i0 + r) * 66 + 2 * k2];
                    acc[r][0] = ffma2(p, h0, acc[r][0]);
                    acc[r][1] = ffma2(p, h1, acc[r][1]);
                }
            }
            #pragma unroll
            for (int r = 0; r < 4; ++r) {
                float x0, y0, x1, y1;
                unpack2(acc[r][0], x0, y0); unpack2(acc[r][1], x1, y1);
                float mv0 = x0 + y0, mv1 = x1 + y1;
                aug[v0 * 162 + 96 + i0 + r] = mv0;
                aug[(v0 + 1) * 162 + 96 + i0 + r] = mv1;
                Md[(i0 + r) * 33 + v0    ] = pack2(-mv0, -mv0);
                Md[(i0 + r) * 33 + v0 + 1] = pack2(-mv1, -mv1);
            }
        }
        if (tid < 136) {   // FPFt = FP @ F^T + Q -> P buffer (sym, f32x2)
            int i0 = tri_i * 4, j0 = tri_j * 4;
            ull acc[4][2];
            #pragma unroll
            for (int r = 0; r < 4; ++r) {
                const float* qp = &Qm[(i0 + r) * 64 + j0];
                acc[r][0] = pack2(qp[0], qp[1]);
                acc[r][1] = pack2(qp[2], qp[3]);
            }
            #pragma unroll 4
            for (int k = 0; k < 64; ++k) {
                ull b0 = *(const ull*)&Ft[k * 66 + j0];
                ull b1 = *(const ull*)&Ft[k * 66 + j0 + 2];
                #pragma unroll
                for (int r = 0; r < 4; ++r) {
                    ull a = FPd[(i0 + r) * 66 + k];
                    acc[r][0] = ffma2(a, b0, acc[r][0]);
                    acc[r][1] = ffma2(a, b1, acc[r][1]);
                }
            }
            #pragma unroll
            for (int r = 0; r < 4; ++r) {
                float v0, v1, v2, v3;
                unpack2(acc[r][0], v0, v1); unpack2(acc[r][1], v2, v3);
                P[(i0 + r) * 66 + j0    ] = v0; P[(j0    ) * 66 + i0 + r] = v0;
                P[(i0 + r) * 66 + j0 + 1] = v1; P[(j0 + 1) * 66 + i0 + r] = v1;
                P[(i0 + r) * 66 + j0 + 2] = v2; P[(j0 + 2) * 66 + i0 + r] = v2;
                P[(i0 + r) * 66 + j0 + 3] = v3; P[(j0 + 3) * 66 + i0 + r] = v3;
            }
        }
        if (tid == 0) red[0] = 0;
        __syncthreads();

        // ======== Phase 3: rank-4 Gauss-Jordan on aug[32][162], cols 0..159
        {
            const int r  = tid >> 3;
            const int jb = tid & 7;
            float* rr = &aug[r * 162];
            for (int piv = 0; piv < 32; piv += 4) {
                float M[4][4], Mi[4][4];
                #pragma unroll
                for (int ii = 0; ii < 4; ++ii)
                    #pragma unroll
                    for (int jj = 0; jj < 4; ++jj)
                        M[ii][jj] = aug[(piv + ii) * 162 + piv + jj];
                inv4(M, Mi);
                float u0 = rr[piv], u1 = rr[piv + 1], u2 = rr[piv + 2], u3 = rr[piv + 3];
                float f0 = u0 * Mi[0][0] + u1 * Mi[1][0] + u2 * Mi[2][0] + u3 * Mi[3][0];
                float f1 = u0 * Mi[0][1] + u1 * Mi[1][1] + u2 * Mi[2][1] + u3 * Mi[3][1];
                float f2 = u0 * Mi[0][2] + u1 * Mi[1][2] + u2 * Mi[2][2] + u3 * Mi[3][2];
                float f3 = u0 * Mi[0][3] + u1 * Mi[1][3] + u2 * Mi[2][3] + u3 * Mi[3][3];
                ull fn0 = pack2(-f0, -f0), fn1 = pack2(-f1, -f1);
                ull fn2 = pack2(-f2, -f2), fn3 = pack2(-f3, -f3);
                __syncwarp();
                if (r < piv || r >= piv + 4) {
                    const float* p0 = &aug[(piv    ) * 162];
                    const float* p1 = &aug[(piv + 1) * 162];
                    const float* p2 = &aug[(piv + 2) * 162];
                    const float* p3 = &aug[(piv + 3) * 162];
                    #pragma unroll
                    for (int tq = 0; tq < 10; ++tq) {
                        int j = 2 * jb + 16 * tq;
                        ull rrj = *(const ull*)&rr[j];
                        rrj = ffma2(fn0, *(const ull*)&p0[j], rrj);
                        rrj = ffma2(fn1, *(const ull*)&p1[j], rrj);
                        rrj = ffma2(fn2, *(const ull*)&p2[j], rrj);
                        rrj = ffma2(fn3, *(const ull*)&p3[j], rrj);
                        *(ull*)&rr[j] = rrj;
                    }
                }
                __syncthreads();
            }
        }

        // ======== Phase 4: block solve -> K (cols 32..95) & Z (96..159) ====
        {
            int blk = tid >> 5;                 // 0..7
            int p   = blk * 4;
            int c0  = 32 + (tid & 31) * 4;      // 4 columns
            float M[4][4], Mi[4][4];
            #pragma unroll
            for (int ii = 0; ii < 4; ++ii)
                #pragma unroll
                for (int jj = 0; jj < 4; ++jj)
                    M[ii][jj] = aug[(p + ii) * 162 + p + jj];
            inv4(M, Mi);
            float lmax = 0.0f;
            #pragma unroll
            for (int cc = 0; cc < 4; ++cc) {
                int c = c0 + cc;
                float r0 = aug[(p + 0) * 162 + c], r1 = aug[(p + 1) * 162 + c];
                float r2 = aug[(p + 2) * 162 + c], r3 = aug[(p + 3) * 162 + c];
                float y0 = Mi[0][0]*r0 + Mi[0][1]*r1 + Mi[0][2]*r2 + Mi[0][3]*r3;
                float y1 = Mi[1][0]*r0 + Mi[1][1]*r1 + Mi[1][2]*r2 + Mi[1][3]*r3;
                float y2 = Mi[2][0]*r0 + Mi[2][1]*r1 + Mi[2][2]*r2 + Mi[2][3]*r3;
                float y3 = Mi[3][0]*r0 + Mi[3][1]*r1 + Mi[3][2]*r2 + Mi[3][3]*r3;
                if (c < 96) {
                    int s = c - 32;
                    float ys[4] = {y0, y1, y2, y3};
                    #pragma unroll
                    for (int q = 0; q < 4; ++q) {
                        int idx = s * 32 + (p + q);
                        g_K[t * (SD * NV) + idx] = ys[q];
                        lmax = fmaxf(lmax, fabsf(ys[q] - Kb[idx]));
                        Kb[idx] = ys[q];
                    }
                } else {
                    int j = c - 96;
                    Zbuf[(p + 0) * 66 + j] = y0;
                    Zbuf[(p + 1) * 66 + j] = y1;
                    Zbuf[(p + 2) * 66 + j] = y2;
                    Zbuf[(p + 3) * 66 + j] = y3;
                }
            }
            #pragma unroll
            for (int off = 16; off; off >>= 1)
                lmax = fmaxf(lmax, __shfl_xor_sync(0xffffffffu, lmax, off));
            if ((tid & 31) == 0) atomicMax(red, __float_as_int(lmax));
        }
        __syncthreads();

        if (t == TT - 2) break;
        if (t >= 6 && __int_as_float(red[0]) < 4e-5f) {
            if (tid == 0) g_tc = t;
            break;
        }

        // ======== Phase 5: P' = FPFt - M Z  (sym lower tiles, f32x2) ======
        if (tid < 136) {
            int i0 = tri_i * 4, j0 = tri_j * 4;
            ull acc[4][2];
            #pragma unroll
            for (int r = 0; r < 4; ++r) {
                const float* up = &P[(i0 + r) * 66 + j0];
                acc[r][0] = pack2(up[0], up[1]);
                acc[r][1] = pack2(up[2], up[3]);
            }
            #pragma unroll 4
            for (int v = 0; v < 32; ++v) {
                ull z0 = *(const ull*)&Zbuf[v * 66 + j0];
                ull z1 = *(const ull*)&Zbuf[v * 66 + j0 + 2];
                #pragma unroll
                for (int r = 0; r < 4; ++r) {
                    ull a = Md[(i0 + r) * 33 + v];   // holds -M duplicated
                    acc[r][0] = ffma2(a, z0, acc[r][0]);
                    acc[r][1] = ffma2(a, z1, acc[r][1]);
                }
            }
            #pragma unroll
            for (int r = 0; r < 4; ++r) {
                float v0, v1, v2, v3;
                unpack2(acc[r][0], v0, v1); unpack2(acc[r][1], v2, v3);
                P[(i0 + r) * 66 + j0    ] = v0; P[(j0    ) * 66 + i0 + r] = v0;
                P[(i0 + r) * 66 + j0 + 1] = v1; P[(j0 + 1) * 66 + i0 + r] = v1;
                P[(i0 + r) * 66 + j0 + 2] = v2; P[(j0 + 2) * 66 + i0 + r] = v2;
                P[(i0 + r) * 66 + j0 + 3] = v3; P[(j0 + 3) * 66 + i0 + r] = v3;
            }
        }
        __syncthreads();
    }
}

// ---------------------------------------------------------------------------
// Build G_t = [[A,B],[HA,HB]] for t <= tc, one CTA per t.
// ---------------------------------------------------------------------------
__global__ __launch_bounds__(256, 1) void kf_buildG(
    const float* __restrict__ Fm, const float* __restrict__ Hm)
{
    const int t = blockIdx.x;
    if (t > g_tc) return;
    extern __shared__ float sm[];
    float* sF  = sm;               // [64][65]
    float* sH  = sF  + 64 * 65;    // [32][65]
    float* sK  = sH  + 32 * 65;    // [64][33]
    float* sFK = sK  + 64 * 33;    // [64][33]
    float* sAB = sFK + 64 * 33;    // [64][97]
    const int tid = threadIdx.x;

    for (int idx = tid; idx < 64 * 64; idx += 256) {
        int i = idx >> 6, j = idx & 63;
        sF[i * 65 + j] = Fm[idx];
    }
    for (int idx = tid; idx < 32 * 64; idx += 256) {
        int i = idx >> 6, j = idx & 63;
        sH[i * 65 + j] = Hm[idx];
    }
    for (int idx = tid; idx < 64 * 32; idx += 256) {
        int s = idx >> 5, v = idx & 31;
        sK[s * 33 + v] = g_K[t * (SD * NV) + idx];
    }
    __syncthreads();

    for (int idx = tid; idx < 64 * 32; idx += 256) {
        int r = idx >> 5, v = idx & 31;
        float a0 = 0, a1 = 0, a2 = 0, a3 = 0;
        #pragma unroll
        for (int s = 0; s < 64; s += 4) {
            a0 += sF[r * 65 + s    ] * sK[(s    ) * 33 + v];
            a1 += sF[r * 65 + s + 1] * sK[(s + 1) * 33 + v];
            a2 += sF[r * 65 + s + 2] * sK[(s + 2) * 33 + v];
            a3 += sF[r * 65 + s + 3] * sK[(s + 3) * 33 + v];
        }
        sFK[r * 33 + v] = (a0 + a1) + (a2 + a3);
    }
    __syncthreads();

    float* gG = g_G + t * 9216;

    {
        int r = tid >> 2, c0 = (tid & 3) * 16;
        float fk[32];
        #pragma unroll
        for (int v = 0; v < 32; ++v) fk[v] = sFK[r * 33 + v];
        float acc[16];
        #pragma unroll
        for (int c = 0; c < 16; ++c) acc[c] = sF[r * 65 + c0 + c];
        #pragma unroll 4
        for (int v = 0; v < 32; ++v) {
            float fkv = fk[v];
            #pragma unroll
            for (int c = 0; c < 16; ++c)
                acc[c] -= fkv * sH[v * 65 + c0 + c];
        }
        #pragma unroll
        for (int c = 0; c < 16; ++c) {
            int cc = c0 + c;
            sAB[r * 97 + cc] = acc[c];
            gG[(cc >> 2) * 384 + r * 4 + (cc & 3)] = acc[c];
        }
    }
    for (int idx = tid; idx < 64 * 32; idx += 256) {
        int r = idx >> 5, v = idx & 31;
        float val = sFK[r * 33 + v];
        int cc = 64 + v;
        sAB[r * 97 + cc] = val;
        gG[(cc >> 2) * 384 + r * 4 + (cc & 3)] = val;
    }
    __syncthreads();

    {
        int w = tid >> 3, c0 = (tid & 7) * 12;
        float acc[12];
        #pragma unroll
        for (int c = 0; c < 12; ++c) acc[c] = 0.0f;
        #pragma unroll 4
        for (int r = 0; r < 64; ++r) {
            float hw = sH[w * 65 + r];
            #pragma unroll
            for (int c = 0; c < 12; ++c)
                acc[c] += hw * sAB[r * 97 + c0 + c];
        }
        #pragma unroll
        for (int c = 0; c < 12; ++c) {
            int cc = c0 + c;
            gG[(cc >> 2) * 384 + (64 + w) * 4 + (cc & 3)] = acc[c];
        }
    }
}

// ---------------------------------------------------------------------------
// Phase 2: one CTA (96 threads) per batch. One dependent stage per step:
// [m_{t+1}; y_{t+1}] = G_t [m_t; o_t].
// ---------------------------------------------------------------------------
__global__ __launch_bounds__(96, 1) void kf_phase2(
    const float* __restrict__ x, float* __restrict__ out)
{
    __shared__ float sx[32 * 129];
    __shared__ float sy[32 * 129];
    __shared__ __align__(16) float z[2][96];

    const int b = blockIdx.x;
    const int tid = threadIdx.x;

    for (int idx = tid; idx < 32 * 128; idx += 96) {
        int v = idx >> 7, tt = idx & 127;
        sx[v * 129 + tt] = x[b * (32 * 128) + idx];
    }
    if (tid < 64) z[0][tid] = 0.0f;
    if (tid < 32) sy[tid * 129 + 0] = 0.0f;
    __syncthreads();
    if (tid >= 64) z[0][tid] = sx[(tid - 64) * 129 + 0];

    const int tc = g_tc;
    const float4* G4 = reinterpret_cast<const float4*>(g_G);
    float4 grow[24];
    #pragma unroll
    for (int q = 0; q < 24; ++q) grow[q] = G4[q * 96 + tid];
    __syncthreads();

    for (int t = 0; t < TT - 1; ++t) {
        const float4* zc4 = reinterpret_cast<const float4*>(z[t & 1]);
        float a0 = 0, a1 = 0, a2 = 0, a3 = 0;
        #pragma unroll
        for (int q = 0; q < 24; q += 4) {
            float4 g0 = grow[q], g1 = grow[q + 1], g2 = grow[q + 2], g3 = grow[q + 3];
            float4 z0 = zc4[q], z1 = zc4[q + 1], z2 = zc4[q + 2], z3 = zc4[q + 3];
            a0 += g0.x * z0.x + g0.y * z0.y + g0.z * z0.z + g0.w * z0.w;
            a1 += g1.x * z1.x + g1.y * z1.y + g1.z * z1.z + g1.w * z1.w;
            a2 += g2.x * z2.x + g2.y * z2.y + g2.z * z2.z + g2.w * z2.w;
            a3 += g3.x * z3.x + g3.y * z3.y + g3.z * z3.z + g3.w * z3.w;
        }
        float acc = (a0 + a1) + (a2 + a3);

        if (t + 1 <= tc) {
            const float4* Gp = G4 + (t + 1) * (24 * 96);
            #pragma unroll
            for (int q = 0; q < 24; ++q) grow[q] = Gp[q * 96 + tid];
        }

        float* zn = z[(t + 1) & 1];
        if (tid < 64) {
            zn[tid] = acc;
        } else {
            int v = tid - 64;
            sy[v * 129 + (t + 1)] = acc;
            zn[tid] = (t < TT - 2) ? sx[v * 129 + (t + 1)] : 0.0f;
        }
        __syncthreads();
    }

    for (int idx = tid; idx < 32 * 128; idx += 96) {
        int v = idx >> 7, tt = idx & 127;
        out[b * (32 * 128) + idx] = sy[v * 129 + tt];
    }
}

extern "C" void kernel_launch(void* const* d_in, const int* in_sizes, int n_in,
                              void* d_out, int out_size)
{
    const float* x = (const float*)d_in[0];
    const float* F = (const float*)d_in[1];
    const float* H = (const float*)d_in[2];
    const float* R = (const float*)d_in[3];
    const float* Q = (const float*)d_in[4];
    float* out = (float*)d_out;

    const int smem1 = (64 * 66 * 2   // F2 dup
                       + 64 * 66     // Ft
                       + 32 * 66     // sH
                       + 64 * 66     // P
                       + 64 * 66 * 2 // FP dup
                       + 64 * 66     // FP plain
                       + 64 * 33     // PHt
                       + 64 * 33 * 2 // -M dup
                       + 32 * 162    // aug
                       + 32 * 66     // Zbuf
                       + 64 * 32     // Kb
                       + 2) * (int)sizeof(float);
    const int smem2 = (64 * 65 + 32 * 65 + 64 * 33 * 2 + 64 * 97)
                      * (int)sizeof(float);
    cudaFuncSetAttribute(kf_phase1, cudaFuncAttributeMaxDynamicSharedMemorySize, smem1);
    cudaFuncSetAttribute(kf_buildG, cudaFuncAttributeMaxDynamicSharedMemorySize, smem2);

    kf_phase1<<<1, 256, smem1>>>(F, H, R, Q);
    kf_buildG<<<TT - 1, 256, smem2>>>(F, H);
    kf_phase2<<<BSZ, 96>>>(x, out);
}

// round 10
// speedup vs baseline: 1.2363x; 1.2363x over previous
#include <cuda_runtime.h>
#include <math.h>

#define TT 128
#define BSZ 128
#define NV 32
#define SD 64

typedef unsigned long long ull;

// Gain matrices K_t (only t <= g_tc valid), layout K[t][(s)*32 + v]
__device__ float g_K[(TT - 1) * SD * NV];
// Combined step operators G_t = [[A,B],[HA,HB]], float4-chunk-major:
// element (row r, col c) of G_t at g_G[t*9216 + (c>>2)*384 + r*4 + (c&3)]
__device__ float g_G[(TT - 1) * 96 * 96];
// Convergence step (last distinct t)
__device__ int g_tc;

__device__ __forceinline__ ull pack2(float x, float y) {
    ull r; asm("mov.b64 %0, {%1, %2};" : "=l"(r) : "f"(x), "f"(y)); return r;
}
__device__ __forceinline__ ull ffma2(ull a, ull b, ull c) {
    ull d; asm("fma.rn.f32x2 %0, %1, %2, %3;" : "=l"(d) : "l"(a), "l"(b), "l"(c));
    return d;
}
__device__ __forceinline__ void unpack2(ull a, float& x, float& y) {
    asm("mov.b64 {%0, %1}, %2;" : "=f"(x), "=f"(y) : "l"(a));
}

// General 4x4 inverse via 2x2 block Schur complement (SPD-safe, no pivoting).
__device__ __forceinline__ void inv4(const float M[4][4], float O[4][4])
{
    float a = M[0][0], b = M[0][1], c = M[1][0], d = M[1][1];
    float idet = 1.0f / (a * d - b * c);
    float Ai00 =  d * idet, Ai01 = -b * idet;
    float Ai10 = -c * idet, Ai11 =  a * idet;
    float B00 = M[0][2], B01 = M[0][3], B10 = M[1][2], B11 = M[1][3];
    float C00 = M[2][0], C01 = M[2][1], C10 = M[3][0], C11 = M[3][1];
    float D00 = M[2][2], D01 = M[2][3], D10 = M[3][2], D11 = M[3][3];
    float AB00 = Ai00 * B00 + Ai01 * B10, AB01 = Ai00 * B01 + Ai01 * B11;
    float AB10 = Ai10 * B00 + Ai11 * B10, AB11 = Ai10 * B01 + Ai11 * B11;
    float CA00 = C00 * Ai00 + C01 * Ai10, CA01 = C00 * Ai01 + C01 * Ai11;
    float CA10 = C10 * Ai00 + C11 * Ai10, CA11 = C10 * Ai01 + C11 * Ai11;
    float S00 = D00 - (C00 * AB00 + C01 * AB10);
    float S01 = D01 - (C00 * AB01 + C01 * AB11);
    float S10 = D10 - (C10 * AB00 + C11 * AB10);
    float S11 = D11 - (C10 * AB01 + C11 * AB11);
    float sdet = 1.0f / (S00 * S11 - S01 * S10);
    float Si00 =  S11 * sdet, Si01 = -S01 * sdet;
    float Si10 = -S10 * sdet, Si11 =  S00 * sdet;
    float SC00 = Si00 * CA00 + Si01 * CA10, SC01 = Si00 * CA01 + Si01 * CA11;
    float SC10 = Si10 * CA00 + Si11 * CA10, SC11 = Si10 * CA01 + Si11 * CA11;
    float AS00 = AB00 * Si00 + AB01 * Si10, AS01 = AB00 * Si01 + AB01 * Si11;
    float AS10 = AB10 * Si00 + AB11 * Si10, AS11 = AB10 * Si01 + AB11 * Si11;
    O[0][0] = Ai00 + AS00 * CA00 + AS01 * CA10;
    O[0][1] = Ai01 + AS00 * CA01 + AS01 * CA11;
    O[1][0] = Ai10 + AS10 * CA00 + AS11 * CA10;
    O[1][1] = Ai11 + AS10 * CA01 + AS11 * CA11;
    O[0][2] = -AS00; O[0][3] = -AS01;
    O[1][2] = -AS10; O[1][3] = -AS11;
    O[2][0] = -SC00; O[2][1] = -SC01;
    O[3][0] = -SC10; O[3][1] = -SC11;
    O[2][2] = Si00; O[2][3] = Si01;
    O[3][2] = Si10; O[3][3] = Si11;
}

// ---------------------------------------------------------------------------
// Phase 1: single CTA, 256 threads. R7 structure (best) + f32x2 on PHt,
// Gauss-Jordan elimination, and T1; R/Q read from L1-cached global.
// ---------------------------------------------------------------------------
__global__ __launch_bounds__(256, 1) void kf_phase1(
    const float* __restrict__ Fm, const float* __restrict__ Hm,
    const float* __restrict__ Rm, const float* __restrict__ Qm)
{
    extern __shared__ float sm[];
    float* F2f  = sm;                   // [64][66] dup (ull view)
    float* Ft   = F2f + 64 * 66 * 2;    // [64][66]  Ft[k][j] = F[j][k]
    float* sH   = Ft  + 64 * 66;        // [32][66]
    float* P    = sH  + 32 * 66;        // [64][66]
    float* T1   = P   + 64 * 66;        // [64][66]
    float* T2f  = T1  + 64 * 66;        // [64][66] dup (ull view)
    float* PHt  = T2f + 64 * 66 * 2;    // [64][33]
    float* PHdf = PHt + 64 * 33;        // [64][33] dup of -PHt (ull view)
    float* aug  = PHdf + 64 * 33 * 2;   // [32][98]  (S | PHt^T), even stride
    float* Kb   = aug + 32 * 98;        // [64*32]
    int*   red  = (int*)(Kb + 64 * 32); // [1]
    ull* F2  = (ull*)F2f;
    ull* T2  = (ull*)T2f;
    ull* PHd = (ull*)PHdf;

    const int tid = threadIdx.x;
    if (tid == 0) g_tc = TT - 2;

    // Lower-triangle 4x4-tile mapping for tid < 136
    int tri_i = 0, tri_j = 0;
    {
        int q = (tid < 136) ? tid : 0;
        tri_i = (int)((sqrtf(8.0f * (float)q + 1.0f) - 1.0f) * 0.5f);
        while ((tri_i + 1) * (tri_i + 2) / 2 <= q) ++tri_i;
        while (tri_i * (tri_i + 1) / 2 > q) --tri_i;
        tri_j = q - tri_i * (tri_i + 1) / 2;
    }

    for (int idx = tid; idx < 64 * 64; idx += 256) {
        int i = idx >> 6, j = idx & 63;
        float f = Fm[idx];
        F2[i * 66 + j] = pack2(f, f);
        Ft[j * 66 + i] = f;
        P [i * 66 + j] = (i == j) ? 1.0f : 0.0f;
    }
    for (int idx = tid; idx < 32 * 64; idx += 256) {
        int i = idx >> 6, j = idx & 63;
        sH[i * 66 + j] = Hm[idx];
    }
    for (int idx = tid; idx < 64 * 32; idx += 256) Kb[idx] = 1e30f;
    __syncthreads();

    const int ty = tid >> 4;   // 0..15
    const int tx = tid & 15;   // 0..15

    for (int t = 0; t < TT - 1; ++t) {
        // ---- PHt[64][32] = P @ H^T  (k-contraction f32x2) + -PHt dup ----
        {
            int i0 = ty * 4, v0 = tx * 2;
            ull acc[4][2];
            #pragma unroll
            for (int r = 0; r < 4; ++r) { acc[r][0] = 0ull; acc[r][1] = 0ull; }
            #pragma unroll 4
            for (int k2 = 0; k2 < 32; ++k2) {
                ull h0 = *(const ull*)&sH[v0 * 66 + 2 * k2];
                ull h1 = *(const ull*)&sH[(v0 + 1) * 66 + 2 * k2];
                #pragma unroll
                for (int r = 0; r < 4; ++r) {
                    ull p = *(const ull*)&P[(i0 + r) * 66 + 2 * k2];
                    acc[r][0] = ffma2(p, h0, acc[r][0]);
                    acc[r][1] = ffma2(p, h1, acc[r][1]);
                }
            }
            #pragma unroll
            for (int r = 0; r < 4; ++r) {
                float x0, y0, x1, y1;
                unpack2(acc[r][0], x0, y0); unpack2(acc[r][1], x1, y1);
                float pv0 = x0 + y0, pv1 = x1 + y1;
                PHt[(i0 + r) * 33 + v0    ] = pv0;
                PHt[(i0 + r) * 33 + v0 + 1] = pv1;
                PHd[(i0 + r) * 33 + v0    ] = pack2(-pv0, -pv0);
                PHd[(i0 + r) * 33 + v0 + 1] = pack2(-pv1, -pv1);
            }
        }
        __syncthreads();

        // ---- aug left = S = H @ PHt + R ; aug right = PHt^T ----
        {
            int i  = tid >> 3;
            int j0 = (tid & 7) * 4;
            float c0 = 0, c1 = 0, c2 = 0, c3 = 0;
            #pragma unroll 8
            for (int k = 0; k < 64; ++k) {
                float a = sH[i * 66 + k];
                const float* bp = &PHt[k * 33 + j0];
                c0 += a * bp[0]; c1 += a * bp[1];
                c2 += a * bp[2]; c3 += a * bp[3];
            }
            const float* rp = &Rm[i * 32 + j0];
            aug[i * 98 + j0    ] = c0 + rp[0];
            aug[i * 98 + j0 + 1] = c1 + rp[1];
            aug[i * 98 + j0 + 2] = c2 + rp[2];
            aug[i * 98 + j0 + 3] = c3 + rp[3];
        }
        for (int idx = tid; idx < 32 * 64; idx += 256) {
            int i = idx >> 6, j = idx & 63;
            aug[i * 98 + 32 + j] = PHt[j * 33 + i];
        }
        __syncthreads();

        // ---- Rank-4 Gauss-Jordan, f32x2 elimination: 8 barriers ----
        {
            const int r  = tid >> 3;
            const int jb = tid & 3;          // note: pairs below use tid&7
            const int jb8 = tid & 7;
            float* rr = &aug[r * 98];
            for (int piv = 0; piv < 32; piv += 4) {
                float M[4][4], Mi[4][4];
                #pragma unroll
                for (int ii = 0; ii < 4; ++ii)
                    #pragma unroll
                    for (int jj = 0; jj < 4; ++jj)
                        M[ii][jj] = aug[(piv + ii) * 98 + piv + jj];
                inv4(M, Mi);
                float u0 = rr[piv], u1 = rr[piv + 1], u2 = rr[piv + 2], u3 = rr[piv + 3];
                float f0 = u0 * Mi[0][0] + u1 * Mi[1][0] + u2 * Mi[2][0] + u3 * Mi[3][0];
                float f1 = u0 * Mi[0][1] + u1 * Mi[1][1] + u2 * Mi[2][1] + u3 * Mi[3][1];
                float f2 = u0 * Mi[0][2] + u1 * Mi[1][2] + u2 * Mi[2][2] + u3 * Mi[3][2];
                float f3 = u0 * Mi[0][3] + u1 * Mi[1][3] + u2 * Mi[2][3] + u3 * Mi[3][3];
                ull fn0 = pack2(-f0, -f0), fn1 = pack2(-f1, -f1);
                ull fn2 = pack2(-f2, -f2), fn3 = pack2(-f3, -f3);
                __syncwarp();
                if (r < piv || r >= piv + 4) {
                    const float* p0 = &aug[(piv    ) * 98];
                    const float* p1 = &aug[(piv + 1) * 98];
                    const float* p2 = &aug[(piv + 2) * 98];
                    const float* p3 = &aug[(piv + 3) * 98];
                    #pragma unroll
                    for (int tq = 0; tq < 6; ++tq) {
                        int j = 2 * jb8 + 16 * tq;      // cols 0..95 as 48 ulls
                        ull rrj = *(const ull*)&rr[j];
                        rrj = ffma2(fn0, *(const ull*)&p0[j], rrj);
                        rrj = ffma2(fn1, *(const ull*)&p1[j], rrj);
                        rrj = ffma2(fn2, *(const ull*)&p2[j], rrj);
                        rrj = ffma2(fn3, *(const ull*)&p3[j], rrj);
                        *(ull*)&rr[j] = rrj;
                    }
                }
                __syncthreads();
            }
            (void)jb;
        }

        // ---- 4x4 block solve of right half: aug_right := S^-1 PHt^T ----
        {
            int blk = tid >> 5;                 // 0..7
            int j   = 32 + (tid & 31) * 2;      // two columns j, j+1
            int p   = blk * 4;
            float M[4][4], Mi[4][4];
            #pragma unroll
            for (int ii = 0; ii < 4; ++ii)
                #pragma unroll
                for (int jj = 0; jj < 4; ++jj)
                    M[ii][jj] = aug[(p + ii) * 98 + p + jj];
            inv4(M, Mi);
            #pragma unroll
            for (int jj = 0; jj < 2; ++jj) {
                float r0 = aug[(p + 0) * 98 + j + jj], r1 = aug[(p + 1) * 98 + j + jj];
                float r2 = aug[(p + 2) * 98 + j + jj], r3 = aug[(p + 3) * 98 + j + jj];
                aug[(p + 0) * 98 + j + jj] = Mi[0][0]*r0 + Mi[0][1]*r1 + Mi[0][2]*r2 + Mi[0][3]*r3;
                aug[(p + 1) * 98 + j + jj] = Mi[1][0]*r0 + Mi[1][1]*r1 + Mi[1][2]*r2 + Mi[1][3]*r3;
                aug[(p + 2) * 98 + j + jj] = Mi[2][0]*r0 + Mi[2][1]*r1 + Mi[2][2]*r2 + Mi[2][3]*r3;
                aug[(p + 3) * 98 + j + jj] = Mi[3][0]*r0 + Mi[3][1]*r1 + Mi[3][2]*r2 + Mi[3][3]*r3;
            }
        }
        if (tid == 0) red[0] = 0;
        __syncthreads();

        // ---- K_t = X^T -> global; track max |dK| ----
        {
            float lmax = 0.0f;
            for (int idx = tid; idx < SD * NV; idx += 256) {
                int s = idx >> 5, v = idx & 31;
                float kv = aug[v * 98 + 32 + s];
                g_K[t * (SD * NV) + idx] = kv;
                lmax = fmaxf(lmax, fabsf(kv - Kb[idx]));
                Kb[idx] = kv;
            }
            #pragma unroll
            for (int off = 16; off; off >>= 1)
                lmax = fmaxf(lmax, __shfl_xor_sync(0xffffffffu, lmax, off));
            if ((tid & 31) == 0) atomicMax(red, __float_as_int(lmax));
        }
        __syncthreads();

        if (t == TT - 2) break;
        if (t >= 6 && __int_as_float(red[0]) < 4e-5f) {
            if (tid == 0) g_tc = t;
            break;
        }

        // ---- T1 = P - PHt @ X  (sym lower tiles + mirror, f32x2) ----
        if (tid < 136) {
            int i0 = tri_i * 4, j0 = tri_j * 4;
            ull acc[4][2];
            #pragma unroll
            for (int r = 0; r < 4; ++r) {
                acc[r][0] = *(const ull*)&P[(i0 + r) * 66 + j0];
                acc[r][1] = *(const ull*)&P[(i0 + r) * 66 + j0 + 2];
            }
            #pragma unroll 4
            for (int v = 0; v < 32; ++v) {
                ull z0 = *(const ull*)&aug[v * 98 + 32 + j0];
                ull z1 = *(const ull*)&aug[v * 98 + 32 + j0 + 2];
                #pragma unroll
                for (int r = 0; r < 4; ++r) {
                    ull a = PHd[(i0 + r) * 33 + v];   // -PHt duplicated
                    acc[r][0] = ffma2(a, z0, acc[r][0]);
                    acc[r][1] = ffma2(a, z1, acc[r][1]);
                }
            }
            #pragma unroll
            for (int r = 0; r < 4; ++r) {
                float v0, v1, v2, v3;
                unpack2(acc[r][0], v0, v1); unpack2(acc[r][1], v2, v3);
                T1[(i0 + r) * 66 + j0    ] = v0; T1[(j0    ) * 66 + i0 + r] = v0;
                T1[(i0 + r) * 66 + j0 + 1] = v1; T1[(j0 + 1) * 66 + i0 + r] = v1;
                T1[(i0 + r) * 66 + j0 + 2] = v2; T1[(j0 + 2) * 66 + i0 + r] = v2;
                T1[(i0 + r) * 66 + j0 + 3] = v3; T1[(j0 + 3) * 66 + i0 + r] = v3;
            }
        }
        __syncthreads();

        // ---- T2 = F @ T1  (full, f32x2: F duplicated, T1 j-paired) ----
        {
            int i0 = ty * 4, j0 = tx * 4;
            ull acc[4][2];
            #pragma unroll
            for (int r = 0; r < 4; ++r) { acc[r][0] = 0ull; acc[r][1] = 0ull; }
            #pragma unroll 4
            for (int k = 0; k < 64; ++k) {
                ull b0 = *(const ull*)&T1[k * 66 + j0];
                ull b1 = *(const ull*)&T1[k * 66 + j0 + 2];
                #pragma unroll
                for (int r = 0; r < 4; ++r) {
                    ull a = F2[(i0 + r) * 66 + k];
                    acc[r][0] = ffma2(a, b0, acc[r][0]);
                    acc[r][1] = ffma2(a, b1, acc[r][1]);
                }
            }
            #pragma unroll
            for (int r = 0; r < 4; ++r) {
                float v0, v1, v2, v3;
                unpack2(acc[r][0], v0, v1); unpack2(acc[r][1], v2, v3);
                T2[(i0 + r) * 66 + j0    ] = pack2(v0, v0);
                T2[(i0 + r) * 66 + j0 + 1] = pack2(v1, v1);
                T2[(i0 + r) * 66 + j0 + 2] = pack2(v2, v2);
                T2[(i0 + r) * 66 + j0 + 3] = pack2(v3, v3);
            }
        }
        __syncthreads();

        // ---- P = T2 @ F^T + Q (sym lower tiles + mirror, f32x2) ----
        if (tid < 136) {
            int i0 = tri_i * 4, j0 = tri_j * 4;
            ull acc[4][2];
            #pragma unroll
            for (int r = 0; r < 4; ++r) {
                const float* qp = &Qm[(i0 + r) * 64 + j0];
                acc[r][0] = pack2(qp[0], qp[1]);
                acc[r][1] = pack2(qp[2], qp[3]);
            }
            #pragma unroll 4
            for (int k = 0; k < 64; ++k) {
                ull b0 = *(const ull*)&Ft[k * 66 + j0];
                ull b1 = *(const ull*)&Ft[k * 66 + j0 + 2];
                #pragma unroll
                for (int r = 0; r < 4; ++r) {
                    ull a = T2[(i0 + r) * 66 + k];
                    acc[r][0] = ffma2(a, b0, acc[r][0]);
                    acc[r][1] = ffma2(a, b1, acc[r][1]);
                }
            }
            #pragma unroll
            for (int r = 0; r < 4; ++r) {
                float v0, v1, v2, v3;
                unpack2(acc[r][0], v0, v1); unpack2(acc[r][1], v2, v3);
                P[(i0 + r) * 66 + j0    ] = v0; P[(j0    ) * 66 + i0 + r] = v0;
                P[(i0 + r) * 66 + j0 + 1] = v1; P[(j0 + 1) * 66 + i0 + r] = v1;
                P[(i0 + r) * 66 + j0 + 2] = v2; P[(j0 + 2) * 66 + i0 + r] = v2;
                P[(i0 + r) * 66 + j0 + 3] = v3; P[(j0 + 3) * 66 + i0 + r] = v3;
            }
        }
        __syncthreads();
    }
}

// ---------------------------------------------------------------------------
// Build G_t = [[A,B],[HA,HB]] for t <= tc, one CTA per t.
// ---------------------------------------------------------------------------
__global__ __launch_bounds__(256, 1) void kf_buildG(
    const float* __restrict__ Fm, const float* __restrict__ Hm)
{
    const int t = blockIdx.x;
    if (t > g_tc) return;
    extern __shared__ float sm[];
    float* sF  = sm;               // [64][65]
    float* sH  = sF  + 64 * 65;    // [32][65]
    float* sK  = sH  + 32 * 65;    // [64][33]
    float* sFK = sK  + 64 * 33;    // [64][33]
    float* sAB = sFK + 64 * 33;    // [64][97]
    const int tid = threadIdx.x;

    for (int idx = tid; idx < 64 * 64; idx += 256) {
        int i = idx >> 6, j = idx & 63;
        sF[i * 65 + j] = Fm[idx];
    }
    for (int idx = tid; idx < 32 * 64; idx += 256) {
        int i = idx >> 6, j = idx & 63;
        sH[i * 65 + j] = Hm[idx];
    }
    for (int idx = tid; idx < 64 * 32; idx += 256) {
        int s = idx >> 5, v = idx & 31;
        sK[s * 33 + v] = g_K[t * (SD * NV) + idx];
    }
    __syncthreads();

    for (int idx = tid; idx < 64 * 32; idx += 256) {
        int r = idx >> 5, v = idx & 31;
        float a0 = 0, a1 = 0, a2 = 0, a3 = 0;
        #pragma unroll
        for (int s = 0; s < 64; s += 4) {
            a0 += sF[r * 65 + s    ] * sK[(s    ) * 33 + v];
            a1 += sF[r * 65 + s + 1] * sK[(s + 1) * 33 + v];
            a2 += sF[r * 65 + s + 2] * sK[(s + 2) * 33 + v];
            a3 += sF[r * 65 + s + 3] * sK[(s + 3) * 33 + v];
        }
        sFK[r * 33 + v] = (a0 + a1) + (a2 + a3);
    }
    __syncthreads();

    float* gG = g_G + t * 9216;

    {
        int r = tid >> 2, c0 = (tid & 3) * 16;
        float fk[32];
        #pragma unroll
        for (int v = 0; v < 32; ++v) fk[v] = sFK[r * 33 + v];
        float acc[16];
        #pragma unroll
        for (int c = 0; c < 16; ++c) acc[c] = sF[r * 65 + c0 + c];
        #pragma unroll 4
        for (int v = 0; v < 32; ++v) {
            float fkv = fk[v];
            #pragma unroll
            for (int c = 0; c < 16; ++c)
                acc[c] -= fkv * sH[v * 65 + c0 + c];
        }
        #pragma unroll
        for (int c = 0; c < 16; ++c) {
            int cc = c0 + c;
            sAB[r * 97 + cc] = acc[c];
            gG[(cc >> 2) * 384 + r * 4 + (cc & 3)] = acc[c];
        }
    }
    for (int idx = tid; idx < 64 * 32; idx += 256) {
        int r = idx >> 5, v = idx & 31;
        float val = sFK[r * 33 + v];
        int cc = 64 + v;
        sAB[r * 97 + cc] = val;
        gG[(cc >> 2) * 384 + r * 4 + (cc & 3)] = val;
    }
    __syncthreads();

    {
        int w = tid >> 3, c0 = (tid & 7) * 12;
        float acc[12];
        #pragma unroll
        for (int c = 0; c < 12; ++c) acc[c] = 0.0f;
        #pragma unroll 4
        for (int r = 0; r < 64; ++r) {
            float hw = sH[w * 65 + r];
            #pragma unroll
            for (int c = 0; c < 12; ++c)
                acc[c] += hw * sAB[r * 97 + c0 + c];
        }
        #pragma unroll
        for (int c = 0; c < 12; ++c) {
            int cc = c0 + c;
            gG[(cc >> 2) * 384 + (64 + w) * 4 + (cc & 3)] = acc[c];
        }
    }
}

// ---------------------------------------------------------------------------
// Phase 2: one CTA (96 threads) per batch. One dependent stage per step:
// [m_{t+1}; y_{t+1}] = G_t [m_t; o_t].
// ---------------------------------------------------------------------------
__global__ __launch_bounds__(96, 1) void kf_phase2(
    const float* __restrict__ x, float* __restrict__ out)
{
    __shared__ float sx[32 * 129];
    __shared__ float sy[32 * 129];
    __shared__ __align__(16) float z[2][96];

    const int b = blockIdx.x;
    const int tid = threadIdx.x;

    for (int idx = tid; idx < 32 * 128; idx += 96) {
        int v = idx >> 7, tt = idx & 127;
        sx[v * 129 + tt] = x[b * (32 * 128) + idx];
    }
    if (tid < 64) z[0][tid] = 0.0f;
    if (tid < 32) sy[tid * 129 + 0] = 0.0f;
    __syncthreads();
    if (tid >= 64) z[0][tid] = sx[(tid - 64) * 129 + 0];

    const int tc = g_tc;
    const float4* G4 = reinterpret_cast<const float4*>(g_G);
    float4 grow[24];
    #pragma unroll
    for (int q = 0; q < 24; ++q) grow[q] = G4[q * 96 + tid];
    __syncthreads();

    for (int t = 0; t < TT - 1; ++t) {
        const float4* zc4 = reinterpret_cast<const float4*>(z[t & 1]);
        float a0 = 0, a1 = 0, a2 = 0, a3 = 0;
        #pragma unroll
        for (int q = 0; q < 24; q += 4) {
            float4 g0 = grow[q], g1 = grow[q + 1], g2 = grow[q + 2], g3 = grow[q + 3];
            float4 z0 = zc4[q], z1 = zc4[q + 1], z2 = zc4[q + 2], z3 = zc4[q + 3];
            a0 += g0.x * z0.x + g0.y * z0.y + g0.z * z0.z + g0.w * z0.w;
            a1 += g1.x * z1.x + g1.y * z1.y + g1.z * z1.z + g1.w * z1.w;
            a2 += g2.x * z2.x + g2.y * z2.y + g2.z * z2.z + g2.w * z2.w;
            a3 += g3.x * z3.x + g3.y * z3.y + g3.z * z3.z + g3.w * z3.w;
        }
        float acc = (a0 + a1) + (a2 + a3);

        if (t + 1 <= tc) {
            const float4* Gp = G4 + (t + 1) * (24 * 96);
            #pragma unroll
            for (int q = 0; q < 24; ++q) grow[q] = Gp[q * 96 + tid];
        }

        float* zn = z[(t + 1) & 1];
        if (tid < 64) {
            zn[tid] = acc;
        } else {
            int v = tid - 64;
            sy[v * 129 + (t + 1)] = acc;
            zn[tid] = (t < TT - 2) ? sx[v * 129 + (t + 1)] : 0.0f;
        }
        __syncthreads();
    }

    for (int idx = tid; idx < 32 * 128; idx += 96) {
        int v = idx >> 7, tt = idx & 127;
        out[b * (32 * 128) + idx] = sy[v * 129 + tt];
    }
}

extern "C" void kernel_launch(void* const* d_in, const int* in_sizes, int n_in,
                              void* d_out, int out_size)
{
    const float* x = (const float*)d_in[0];
    const float* F = (const float*)d_in[1];
    const float* H = (const float*)d_in[2];
    const float* R = (const float*)d_in[3];
    const float* Q = (const float*)d_in[4];
    float* out = (float*)d_out;

    const int smem1 = (64 * 66 * 2   // F2 dup
                       + 64 * 66     // Ft
                       + 32 * 66     // sH
                       + 64 * 66     // P
                       + 64 * 66     // T1
                       + 64 * 66 * 2 // T2 dup
                       + 64 * 33     // PHt
                       + 64 * 33 * 2 // -PHt dup
                       + 32 * 98     // aug
                       + 64 * 32     // Kb
                       + 2) * (int)sizeof(float);
    const int smem2 = (64 * 65 + 32 * 65 + 64 * 33 * 2 + 64 * 97)
                      * (int)sizeof(float);
    cudaFuncSetAttribute(kf_phase1, cudaFuncAttributeMaxDynamicSharedMemorySize, smem1);
    cudaFuncSetAttribute(kf_buildG, cudaFuncAttributeMaxDynamicSharedMemorySize, smem2);

    kf_phase1<<<1, 256, smem1>>>(F, H, R, Q);
    kf_buildG<<<TT - 1, 256, smem2>>>(F, H);
    kf_phase2<<<BSZ, 96>>>(x, out);
}